// round 13
// baseline (speedup 1.0000x reference)
#include <cuda_runtime.h>

// ---------------------------------------------------------------------------
// BettingLoss, warp-specialized TMA producer + free-running consumers.
// R10 post-mortem: LDG/cp.async/TMA producers ALL plateau at ~5TB/s (62%),
// so the producer mechanism isn't the limiter. Accounting shows 2.24us/iter
// vs 1.68us DRAM-ideal: the lockstep consume->syncthreads->refill loop leaves
// DRAM idle between block-wide fill bursts. Fix: dedicated producer warp with
// per-stage empty mbarriers; consumers never block-sync in the loop.
// ---------------------------------------------------------------------------

static __device__ double             g_sum_bet_ep;    // zero-init at load,
static __device__ double             g_batch_profit;  // reset by last block
static __device__ double             g_sum_maxprob;
static __device__ unsigned long long g_num_bets;
static __device__ unsigned int       g_block_count;   // self-wrapping ticket

constexpr int      THREADS    = 544;                  // 1 producer warp + 512
constexpr int      CONSUMERS  = 512;
constexpr int      TILE_ROWS  = 512;                  // rows per stage
constexpr unsigned ARR_BYTES  = TILE_ROWS * 24u;      // 12288 B per array
constexpr unsigned STAGE_B    = 3u * ARR_BYTES;       // 36864 B per stage
constexpr int      STAGES     = 3;
constexpr unsigned SMEM_DYN   = STAGES * STAGE_B;     // 110592 B

// One race (6 traps).
__device__ __forceinline__ void process_row(const float* __restrict__ p,
                                            const float* __restrict__ w,
                                            const float* __restrict__ o,
                                            float& ep_acc, float& pr_acc,
                                            float& mp_acc, int& nb)
{
    const float A   = 1.1f;    // ALPHA
    const float PAY = 0.019f;  // BET_PCT * (1 - COMMISSION)

    // Strict rounding (no FMA contraction) to match XLA f32 at the ep>0 edge.
    float best = __fmul_rn(__fsub_rn(__fmul_rn(__fmul_rn(o[0], A), p[0]), 1.0f), PAY);
    float bo   = o[0];
    float bw   = w[0];
    float mx   = p[0];
    bool  valid = (o[0] > 0.0f);

#pragma unroll
    for (int i = 1; i < 6; ++i) {
        float ep = __fmul_rn(__fsub_rn(__fmul_rn(__fmul_rn(o[i], A), p[i]), 1.0f), PAY);
        if (ep > best) {       // strict '>' => first-max like jnp.argmax
            best = ep; bo = o[i]; bw = w[i];
        }
        mx    = fmaxf(mx, p[i]);
        valid = valid || (o[i] > 0.0f);
    }

    mp_acc += mx;              // fallback term needs row-max for ALL rows

    if (valid && best > 0.0f) {
        ep_acc += best;
        nb     += 1;
        float win_profit = __fmul_rn(__fsub_rn(__fmul_rn(__fmul_rn(bo, A), 0.02f),
                                               0.02f), 0.95f);
        pr_acc += (bw > 0.5f) ? win_profit : -0.019f;
    }
}

// Producer lane: arm tx-barrier, issue 3 bulk copies (one per array).
__device__ __forceinline__ void tma_fill(unsigned mbar, unsigned sdst,
                                         const char* __restrict__ pB,
                                         const char* __restrict__ oB,
                                         const char* __restrict__ wB,
                                         long long tile)
{
    long long off = tile * (long long)ARR_BYTES;
    asm volatile("mbarrier.arrive.expect_tx.shared.b64 _, [%0], %1;"
                 :: "r"(mbar), "r"(STAGE_B) : "memory");
    asm volatile("cp.async.bulk.shared::cluster.global.mbarrier::complete_tx::bytes"
                 " [%0], [%1], %2, [%3];"
                 :: "r"(sdst),                 "l"(pB + off), "r"(ARR_BYTES),
                    "r"(mbar) : "memory");
    asm volatile("cp.async.bulk.shared::cluster.global.mbarrier::complete_tx::bytes"
                 " [%0], [%1], %2, [%3];"
                 :: "r"(sdst + ARR_BYTES),     "l"(oB + off), "r"(ARR_BYTES),
                    "r"(mbar) : "memory");
    asm volatile("cp.async.bulk.shared::cluster.global.mbarrier::complete_tx::bytes"
                 " [%0], [%1], %2, [%3];"
                 :: "r"(sdst + 2 * ARR_BYTES), "l"(wB + off), "r"(ARR_BYTES),
                    "r"(mbar) : "memory");
}

__device__ __forceinline__ void mbar_wait(unsigned mbar, unsigned parity)
{
    asm volatile(
        "{\n\t"
        ".reg .pred P;\n\t"
        "WAIT_%=:\n\t"
        "mbarrier.try_wait.parity.acquire.cta.shared::cta.b64 P, [%0], %1, 0x989680;\n\t"
        "@P bra DONE_%=;\n\t"
        "bra WAIT_%=;\n\t"
        "DONE_%=:\n\t"
        "}" :: "r"(mbar), "r"(parity) : "memory");
}

extern __shared__ float s_dyn[];                      // STAGES * 36864 B

__global__ void __launch_bounds__(THREADS)
betting_ws_kernel(const float* __restrict__ probs,
                  const float* __restrict__ winners,
                  const float* __restrict__ odds,
                  long long ntiles, long long rows,
                  float* __restrict__ out, int out_size, double invB)
{
    // barriers: [0..2] full (tx), [3..5] empty (512 consumer arrivals)
    __shared__ __align__(8) unsigned long long s_mbar[2 * STAGES];
    __shared__ double re[17], rp[17], rm[17];
    __shared__ int    rn[17];

    const int tid = threadIdx.x;
    unsigned sbase = (unsigned)__cvta_generic_to_shared(s_dyn);
    unsigned mfull = (unsigned)__cvta_generic_to_shared(s_mbar);
    unsigned mempt = mfull + 8u * STAGES;

    const char* pB = (const char*)probs;
    const char* oB = (const char*)odds;
    const char* wB = (const char*)winners;

    if (tid == 0) {
#pragma unroll
        for (int s = 0; s < STAGES; ++s) {
            asm volatile("mbarrier.init.shared.b64 [%0], 1;"
                         :: "r"(mfull + 8u * s) : "memory");
            asm volatile("mbarrier.init.shared.b64 [%0], %1;"
                         :: "r"(mempt + 8u * s), "r"(CONSUMERS) : "memory");
        }
    }
    __syncthreads();
    asm volatile("fence.proxy.async.shared::cta;" ::: "memory");

    const long long g  = gridDim.x;
    const long long t0 = blockIdx.x;
    // number of tiles this block consumes
    const long long cnt = (t0 < ntiles) ? (ntiles - t0 + g - 1) / g : 0;

    double de = 0.0, dp = 0.0, dm = 0.0;
    int    nb = 0;

    if (tid < 32) {
        // ---------------- producer warp (lane 0 acts) ----------------
        if (tid == 0) {
            int fs = 0;
            unsigned round = 0;
            for (long long k = 0; k < cnt; ++k) {
                if (k >= STAGES)                       // stage reuse: wait free
                    mbar_wait(mempt + 8u * fs, (round - 1) & 1u);
                asm volatile("fence.proxy.async.shared::cta;" ::: "memory");
                tma_fill(mfull + 8u * fs, sbase + (unsigned)fs * STAGE_B,
                         pB, oB, wB, t0 + k * g);
                if (++fs == STAGES) { fs = 0; ++round; }
            }
        }
    } else {
        // ---------------- consumers (512 threads) ----------------
        const int ctid = tid - 32;

        // remainder rows (rows % TILE_ROWS) via direct loads, block 0 only
        if (blockIdx.x == 0) {
            long long full_r = ntiles * TILE_ROWS;
            for (long long r = full_r + ctid; r < rows; r += CONSUMERS) {
                long long b6 = r * 6;
                float p[6], w[6], o[6];
#pragma unroll
                for (int i = 0; i < 6; ++i) {
                    p[i] = probs[b6 + i]; w[i] = winners[b6 + i];
                    o[i] = odds[b6 + i];
                }
                float ep = 0.f, pr = 0.f, mp = 0.f; int n1 = 0;
                process_row(p, w, o, ep, pr, mp, n1);
                de += ep; dp += pr; dm += mp; nb += n1;
            }
        }

        int cs = 0;
        unsigned cph = 0;
        for (long long k = 0; k < cnt; ++k) {
            mbar_wait(mfull + 8u * cs, cph);           // acquire: TMA data ready

            const float* S  = s_dyn + (unsigned)cs * (STAGE_B / 4u);
            const float* sp = S + ctid * 6;
            const float* so = S + (ARR_BYTES / 4u)     + ctid * 6;
            const float* sw = S + (ARR_BYTES / 4u) * 2 + ctid * 6;

            float ep = 0.f, pr = 0.f, mp = 0.f; int n1 = 0;
            process_row(sp, sw, so, ep, pr, mp, n1);
            de += (double)ep; dp += (double)pr; dm += (double)mp; nb += n1;

            // release: this thread is done reading stage cs
            asm volatile("mbarrier.arrive.shared.b64 _, [%0];"
                         :: "r"(mempt + 8u * cs) : "memory");

            if (++cs == STAGES) { cs = 0; cph ^= 1u; }
        }
    }

    // ---- block reduction: warp shuffle (double) -> smem -> 1 atomic set ----
    const unsigned full_m = 0xffffffffu;
#pragma unroll
    for (int off = 16; off > 0; off >>= 1) {
        de += __shfl_down_sync(full_m, de, off);
        dp += __shfl_down_sync(full_m, dp, off);
        dm += __shfl_down_sync(full_m, dm, off);
        nb += __shfl_down_sync(full_m, nb, off);
    }
    int warp = tid >> 5;
    int lane = tid & 31;
    if (lane == 0) { re[warp] = de; rp[warp] = dp; rm[warp] = dm; rn[warp] = nb; }
    __syncthreads();

    if (warp == 0) {
        de = (lane < 17) ? re[lane] : 0.0;
        dp = (lane < 17) ? rp[lane] : 0.0;
        dm = (lane < 17) ? rm[lane] : 0.0;
        nb = (lane < 17) ? rn[lane] : 0;
#pragma unroll
        for (int off = 16; off > 0; off >>= 1) {
            de += __shfl_down_sync(full_m, de, off);
            dp += __shfl_down_sync(full_m, dp, off);
            dm += __shfl_down_sync(full_m, dm, off);
            nb += __shfl_down_sync(full_m, nb, off);
        }
        if (lane == 0) {
            atomicAdd(&g_sum_bet_ep,   de);
            atomicAdd(&g_batch_profit, dp);
            atomicAdd(&g_sum_maxprob,  dm);
            atomicAdd(&g_num_bets, (unsigned long long)nb);

            // ---- last-block finalize + reset (graph-replay safe) ----
            __threadfence();
            unsigned ticket = atomicInc(&g_block_count, gridDim.x - 1);
            if (ticket == gridDim.x - 1) {
                __threadfence();
                double e = atomicAdd(&g_sum_bet_ep,   0.0);
                double p = atomicAdd(&g_batch_profit, 0.0);
                double m = atomicAdd(&g_sum_maxprob,  0.0);
                unsigned long long cnt2 = atomicAdd(&g_num_bets, 0ull);

                double total = (cnt2 > 0ull) ? e : -(m * invB) * 0.1;
                out[0] = (float)(-(total * invB));            // loss
                if (out_size >= 3) {
                    out[1] = (float)p;                        // batch_profit
                    out[2] = (float)cnt2;                     // num_bets
                }
                atomicExch((unsigned long long*)&g_sum_bet_ep,   0ull);
                atomicExch((unsigned long long*)&g_batch_profit, 0ull);
                atomicExch((unsigned long long*)&g_sum_maxprob,  0ull);
                atomicExch(&g_num_bets, 0ull);
                // g_block_count wrapped to 0 by atomicInc
            }
        }
    }
}

extern "C" void kernel_launch(void* const* d_in, const int* in_sizes, int n_in,
                              void* d_out, int out_size)
{
    const float* probs   = (const float*)d_in[0];  // predicted_probs [B,6]
    const float* winners = (const float*)d_in[1];  // true_winners    [B,6]
    const float* odds    = (const float*)d_in[2];  // market_odds     [B,6]

    long long n      = (long long)in_sizes[0];
    long long rows   = n / 6;
    long long ntiles = rows / TILE_ROWS;           // full tiles only

    static int attr_done = 0;
    if (!attr_done) {
        cudaFuncSetAttribute(betting_ws_kernel,
                             cudaFuncAttributeMaxDynamicSharedMemorySize,
                             (int)SMEM_DYN);
        attr_done = 1;
    }

    long long blocks = 148LL * 2;                  // 2 CTAs/SM (110.6KB each)
    if (blocks > ntiles) blocks = ntiles;
    if (blocks < 1) blocks = 1;

    betting_ws_kernel<<<(unsigned)blocks, THREADS, SMEM_DYN>>>(
        probs, winners, odds, ntiles, rows,
        (float*)d_out, out_size, 1.0 / (double)rows);
}

// round 17
// speedup vs baseline: 1.3163x; 1.3163x over previous
#include <cuda_runtime.h>

// ---------------------------------------------------------------------------
// BettingLoss, persistent barrier-free register-pipelined streaming kernel.
// R12 post-mortem: all smem-staged pipelines (cp.async / TMA / warp-spec)
// plateau at 59-63% DRAM with nothing saturated -- consumer issue streams
// pause at every stage boundary. This version has NO barriers and NO smem
// staging: each thread ping-pongs two register buffers, so the 9 independent
// LDG.128 for pair i+stride are in flight while pair i is processed. L1
// wavefront amplification of the 48B stride is 3x but still sustains
// >= HBM peak (42.7 useful B/cyc/SM x 148 >= LTS cap), so DRAM is the wall.
// ---------------------------------------------------------------------------

static __device__ double             g_sum_bet_ep;    // zero-init at load,
static __device__ double             g_batch_profit;  // reset by last block
static __device__ double             g_sum_maxprob;
static __device__ unsigned long long g_num_bets;
static __device__ unsigned int       g_block_count;   // self-wrapping ticket

constexpr int THREADS = 256;

// One race (6 traps) from registers.
__device__ __forceinline__ void process_row(const float* __restrict__ p,
                                            const float* __restrict__ w,
                                            const float* __restrict__ o,
                                            float& ep_acc, float& pr_acc,
                                            float& mp_acc, int& nb)
{
    const float A   = 1.1f;    // ALPHA
    const float PAY = 0.019f;  // BET_PCT * (1 - COMMISSION)

    // Strict rounding (no FMA contraction) to match XLA f32 at the ep>0 edge.
    float best = __fmul_rn(__fsub_rn(__fmul_rn(__fmul_rn(o[0], A), p[0]), 1.0f), PAY);
    float bo   = o[0];
    float bw   = w[0];
    float mx   = p[0];
    bool  valid = (o[0] > 0.0f);

#pragma unroll
    for (int i = 1; i < 6; ++i) {
        float ep = __fmul_rn(__fsub_rn(__fmul_rn(__fmul_rn(o[i], A), p[i]), 1.0f), PAY);
        if (ep > best) {       // strict '>' => first-max like jnp.argmax
            best = ep; bo = o[i]; bw = w[i];
        }
        mx    = fmaxf(mx, p[i]);
        valid = valid || (o[i] > 0.0f);
    }

    mp_acc += mx;              // fallback term needs row-max for ALL rows

    if (valid && best > 0.0f) {
        ep_acc += best;
        nb     += 1;
        float win_profit = __fmul_rn(__fsub_rn(__fmul_rn(__fmul_rn(bo, A), 0.02f),
                                               0.02f), 0.95f);
        pr_acc += (bw > 0.5f) ? win_profit : -0.019f;
    }
}

struct PairBuf { float4 p[3], o[3], w[3]; };          // 2 rows = 48B/array

// 9 independent streaming loads (MLP 9). idx pre-clamped by caller.
__device__ __forceinline__ void load_pair(PairBuf& b, long long idx,
                                          const float4* __restrict__ P4,
                                          const float4* __restrict__ O4,
                                          const float4* __restrict__ W4)
{
    long long v = idx * 3;
#pragma unroll
    for (int k = 0; k < 3; ++k) b.p[k] = __ldcs(P4 + v + k);
#pragma unroll
    for (int k = 0; k < 3; ++k) b.o[k] = __ldcs(O4 + v + k);
#pragma unroll
    for (int k = 0; k < 3; ++k) b.w[k] = __ldcs(W4 + v + k);
}

__device__ __forceinline__ void proc_pair(const PairBuf& b,
                                          float& ep, float& pr, float& mp, int& nb)
{
    const float* p = (const float*)b.p;
    const float* o = (const float*)b.o;
    const float* w = (const float*)b.w;
    process_row(p,     w,     o,     ep, pr, mp, nb);
    process_row(p + 6, w + 6, o + 6, ep, pr, mp, nb);
}

__global__ void __launch_bounds__(THREADS)
betting_flat_kernel(const float* __restrict__ probs,
                    const float* __restrict__ winners,
                    const float* __restrict__ odds,
                    long long pairs, long long rows,
                    float* __restrict__ out, int out_size, double invB)
{
    __shared__ double re[8], rp[8], rm[8];
    __shared__ int    rn[8];

    const float4* __restrict__ P4 = (const float4*)probs;
    const float4* __restrict__ O4 = (const float4*)odds;
    const float4* __restrict__ W4 = (const float4*)winners;

    const long long stride = (long long)gridDim.x * THREADS;
    const int tid = threadIdx.x;

    float ep = 0.f, pr = 0.f, mp = 0.f;
    int   nb = 0;

    long long i = (long long)blockIdx.x * THREADS + tid;

    PairBuf A, Bf;
    if (i < pairs) {
        load_pair(A, i, P4, O4, W4);
        // ping-pong: process A while B's loads are in flight, and vice versa.
        for (;;) {
            long long j = i + stride;
            bool okB = (j < pairs);
            load_pair(Bf, okB ? j : 0, P4, O4, W4);   // clamped dummy if OOB
            proc_pair(A, ep, pr, mp, nb);
            if (!okB) break;

            long long k = j + stride;
            bool okA = (k < pairs);
            load_pair(A, okA ? k : 0, P4, O4, W4);
            proc_pair(Bf, ep, pr, mp, nb);
            if (!okA) break;
            i = k;
        }
    }

    // odd final row (rows odd): thread 0 of block 0, scalar path
    if ((rows & 1) && blockIdx.x == 0 && tid == 0) {
        long long b6 = (rows - 1) * 6;
        float p[6], w[6], o[6];
#pragma unroll
        for (int q = 0; q < 6; ++q) {
            p[q] = probs[b6 + q]; w[q] = winners[b6 + q]; o[q] = odds[b6 + q];
        }
        process_row(p, w, o, ep, pr, mp, nb);
    }

    // ---- block reduction: warp shuffle (double) -> smem -> 1 atomic set ----
    double de = (double)ep, dp = (double)pr, dm = (double)mp;
    const unsigned full_m = 0xffffffffu;
#pragma unroll
    for (int off = 16; off > 0; off >>= 1) {
        de += __shfl_down_sync(full_m, de, off);
        dp += __shfl_down_sync(full_m, dp, off);
        dm += __shfl_down_sync(full_m, dm, off);
        nb += __shfl_down_sync(full_m, nb, off);
    }
    int warp = tid >> 5;
    int lane = tid & 31;
    if (lane == 0) { re[warp] = de; rp[warp] = dp; rm[warp] = dm; rn[warp] = nb; }
    __syncthreads();

    if (warp == 0) {
        de = (lane < 8) ? re[lane] : 0.0;
        dp = (lane < 8) ? rp[lane] : 0.0;
        dm = (lane < 8) ? rm[lane] : 0.0;
        nb = (lane < 8) ? rn[lane] : 0;
#pragma unroll
        for (int off = 4; off > 0; off >>= 1) {
            de += __shfl_down_sync(full_m, de, off);
            dp += __shfl_down_sync(full_m, dp, off);
            dm += __shfl_down_sync(full_m, dm, off);
            nb += __shfl_down_sync(full_m, nb, off);
        }
        if (lane == 0) {
            atomicAdd(&g_sum_bet_ep,   de);
            atomicAdd(&g_batch_profit, dp);
            atomicAdd(&g_sum_maxprob,  dm);
            atomicAdd(&g_num_bets, (unsigned long long)nb);

            // ---- last-block finalize + reset (graph-replay safe) ----
            __threadfence();
            unsigned ticket = atomicInc(&g_block_count, gridDim.x - 1);
            if (ticket == gridDim.x - 1) {
                __threadfence();
                double e = atomicAdd(&g_sum_bet_ep,   0.0);
                double p = atomicAdd(&g_batch_profit, 0.0);
                double m = atomicAdd(&g_sum_maxprob,  0.0);
                unsigned long long cnt = atomicAdd(&g_num_bets, 0ull);

                double total = (cnt > 0ull) ? e : -(m * invB) * 0.1;
                out[0] = (float)(-(total * invB));            // loss
                if (out_size >= 3) {
                    out[1] = (float)p;                        // batch_profit
                    out[2] = (float)cnt;                      // num_bets
                }
                atomicExch((unsigned long long*)&g_sum_bet_ep,   0ull);
                atomicExch((unsigned long long*)&g_batch_profit, 0ull);
                atomicExch((unsigned long long*)&g_sum_maxprob,  0ull);
                atomicExch(&g_num_bets, 0ull);
                // g_block_count wrapped to 0 by atomicInc
            }
        }
    }
}

extern "C" void kernel_launch(void* const* d_in, const int* in_sizes, int n_in,
                              void* d_out, int out_size)
{
    const float* probs   = (const float*)d_in[0];  // predicted_probs [B,6]
    const float* winners = (const float*)d_in[1];  // true_winners    [B,6]
    const float* odds    = (const float*)d_in[2];  // market_odds     [B,6]

    long long n     = (long long)in_sizes[0];
    long long rows  = n / 6;
    long long pairs = rows / 2;

    // persistent: 2 CTAs/SM resident (<=128 regs @ 256 thr guaranteed)
    long long blocks = 148LL * 2;
    long long maxb   = (pairs + THREADS - 1) / THREADS;
    if (blocks > maxb) blocks = maxb;
    if (blocks < 1) blocks = 1;

    betting_flat_kernel<<<(unsigned)blocks, THREADS>>>(
        probs, winners, odds, pairs, rows,
        (float*)d_out, out_size, 1.0 / (double)rows);
}